// round 2
// baseline (speedup 1.0000x reference)
#include <cuda_runtime.h>
#include <math.h>

// Problem constants
#define TT   64
#define BB   1024
#define DZc  256
#define DXc  64
#define DHc  1024

#define ROWS 8                 // batch rows per CTA
#define NCTA (BB / ROWS)       // 128 CTAs
#define NTH  256               // threads per CTA

// Dynamic shared memory layout (in floats)
#define OFF_Z    0
#define OFF_ZIN  (ROWS * DZc)
#define OFF_KSUM (2 * ROWS * DZc)
#define OFF_XB   (3 * ROWS * DZc)
#define OFF_H    (3 * ROWS * DZc + ROWS * DHc)
#define OFF_XS   (3 * ROWS * DZc + 2 * ROWS * DHc)
#define SMEM_FLOATS (3 * ROWS * DZc + 2 * ROWS * DHc + ROWS * DXc)

// ---------------------------------------------------------------------------
// GEMM1: h = tanh(zin @ W1 + xb + ts * wt)
// Thread t owns columns [4t, 4t+4) of DH for all 8 rows (32 accumulators).
// W1 rows streamed via float4 (coalesced 512B/warp), zin via broadcast LDS.128.
// ---------------------------------------------------------------------------
__device__ __forceinline__ void gemm1_tanh(
    const float* zin_s, const float* xb_s,
    const float* __restrict__ W1, const float* __restrict__ wt,
    float ts, float* h_s)
{
    const int c0 = threadIdx.x * 4;
    float acc[ROWS][4];
#pragma unroll
    for (int r = 0; r < ROWS; ++r)
#pragma unroll
        for (int c = 0; c < 4; ++c) acc[r][c] = 0.f;

#pragma unroll 2
    for (int k = 0; k < DZc; k += 4) {
        const float4 w0 = *(const float4*)(W1 + (k + 0) * DHc + c0);
        const float4 w1 = *(const float4*)(W1 + (k + 1) * DHc + c0);
        const float4 w2 = *(const float4*)(W1 + (k + 2) * DHc + c0);
        const float4 w3 = *(const float4*)(W1 + (k + 3) * DHc + c0);
#pragma unroll
        for (int r = 0; r < ROWS; ++r) {
            const float4 zv = *(const float4*)(zin_s + r * DZc + k);
            acc[r][0] = fmaf(zv.x, w0.x, acc[r][0]);
            acc[r][1] = fmaf(zv.x, w0.y, acc[r][1]);
            acc[r][2] = fmaf(zv.x, w0.z, acc[r][2]);
            acc[r][3] = fmaf(zv.x, w0.w, acc[r][3]);
            acc[r][0] = fmaf(zv.y, w1.x, acc[r][0]);
            acc[r][1] = fmaf(zv.y, w1.y, acc[r][1]);
            acc[r][2] = fmaf(zv.y, w1.z, acc[r][2]);
            acc[r][3] = fmaf(zv.y, w1.w, acc[r][3]);
            acc[r][0] = fmaf(zv.z, w2.x, acc[r][0]);
            acc[r][1] = fmaf(zv.z, w2.y, acc[r][1]);
            acc[r][2] = fmaf(zv.z, w2.z, acc[r][2]);
            acc[r][3] = fmaf(zv.z, w2.w, acc[r][3]);
            acc[r][0] = fmaf(zv.w, w3.x, acc[r][0]);
            acc[r][1] = fmaf(zv.w, w3.y, acc[r][1]);
            acc[r][2] = fmaf(zv.w, w3.z, acc[r][2]);
            acc[r][3] = fmaf(zv.w, w3.w, acc[r][3]);
        }
    }

    const float4 wtv = *(const float4*)(wt + c0);
#pragma unroll
    for (int r = 0; r < ROWS; ++r) {
        const float4 xbv = *(const float4*)(xb_s + r * DHc + c0);
        float4 hv;
        hv.x = tanhf(acc[r][0] + xbv.x + ts * wtv.x);
        hv.y = tanhf(acc[r][1] + xbv.y + ts * wtv.y);
        hv.z = tanhf(acc[r][2] + xbv.z + ts * wtv.z);
        hv.w = tanhf(acc[r][3] + xbv.w + ts * wtv.w);
        *(float4*)(h_s + r * DHc + c0) = hv;
    }
}

// ---------------------------------------------------------------------------
// xb = xs @ Wx + b1   (once per time step; same mapping as GEMM1, K = DX = 64)
// ---------------------------------------------------------------------------
__device__ __forceinline__ void gemm_xb(
    const float* xs_s, const float* __restrict__ Wx,
    const float* __restrict__ b1, float* xb_s)
{
    const int c0 = threadIdx.x * 4;
    float acc[ROWS][4];
#pragma unroll
    for (int r = 0; r < ROWS; ++r)
#pragma unroll
        for (int c = 0; c < 4; ++c) acc[r][c] = 0.f;

#pragma unroll 2
    for (int k = 0; k < DXc; k += 4) {
        const float4 w0 = *(const float4*)(Wx + (k + 0) * DHc + c0);
        const float4 w1 = *(const float4*)(Wx + (k + 1) * DHc + c0);
        const float4 w2 = *(const float4*)(Wx + (k + 2) * DHc + c0);
        const float4 w3 = *(const float4*)(Wx + (k + 3) * DHc + c0);
#pragma unroll
        for (int r = 0; r < ROWS; ++r) {
            const float4 xv = *(const float4*)(xs_s + r * DXc + k);
            acc[r][0] = fmaf(xv.x, w0.x, acc[r][0]);
            acc[r][1] = fmaf(xv.x, w0.y, acc[r][1]);
            acc[r][2] = fmaf(xv.x, w0.z, acc[r][2]);
            acc[r][3] = fmaf(xv.x, w0.w, acc[r][3]);
            acc[r][0] = fmaf(xv.y, w1.x, acc[r][0]);
            acc[r][1] = fmaf(xv.y, w1.y, acc[r][1]);
            acc[r][2] = fmaf(xv.y, w1.z, acc[r][2]);
            acc[r][3] = fmaf(xv.y, w1.w, acc[r][3]);
            acc[r][0] = fmaf(xv.z, w2.x, acc[r][0]);
            acc[r][1] = fmaf(xv.z, w2.y, acc[r][1]);
            acc[r][2] = fmaf(xv.z, w2.z, acc[r][2]);
            acc[r][3] = fmaf(xv.z, w2.w, acc[r][3]);
            acc[r][0] = fmaf(xv.w, w3.x, acc[r][0]);
            acc[r][1] = fmaf(xv.w, w3.y, acc[r][1]);
            acc[r][2] = fmaf(xv.w, w3.z, acc[r][2]);
            acc[r][3] = fmaf(xv.w, w3.w, acc[r][3]);
        }
    }

    const float4 b1v = *(const float4*)(b1 + c0);
#pragma unroll
    for (int r = 0; r < ROWS; ++r) {
        float4 v;
        v.x = acc[r][0] + b1v.x;
        v.y = acc[r][1] + b1v.y;
        v.z = acc[r][2] + b1v.z;
        v.w = acc[r][3] + b1v.w;
        *(float4*)(xb_s + r * DHc + c0) = v;
    }
}

// ---------------------------------------------------------------------------
// GEMM2 + RK4 epilogue: k = h @ W2 + b2, then update ksum / zin / z.
// Thread t owns column t of DZ for all 8 rows (8 accumulators).
// W2 row read once per CTA per k (coalesced 1KB), h via broadcast LDS.128.
// MODE: 0=k1, 1=k2, 2=k3, 3=k4(final combine)
// ---------------------------------------------------------------------------
template <int MODE>
__device__ __forceinline__ void gemm2_update(
    const float* h_s, const float* __restrict__ W2, const float* __restrict__ b2,
    float* z_s, float* zin_s, float* ksum_s, float hstep)
{
    const int j = threadIdx.x;
    float acc[ROWS];
#pragma unroll
    for (int r = 0; r < ROWS; ++r) acc[r] = 0.f;

#pragma unroll 4
    for (int k = 0; k < DHc; k += 4) {
        const float w0 = __ldg(W2 + (k + 0) * DZc + j);
        const float w1 = __ldg(W2 + (k + 1) * DZc + j);
        const float w2 = __ldg(W2 + (k + 2) * DZc + j);
        const float w3 = __ldg(W2 + (k + 3) * DZc + j);
#pragma unroll
        for (int r = 0; r < ROWS; ++r) {
            const float4 hv = *(const float4*)(h_s + r * DHc + k);
            acc[r] = fmaf(hv.x, w0, acc[r]);
            acc[r] = fmaf(hv.y, w1, acc[r]);
            acc[r] = fmaf(hv.z, w2, acc[r]);
            acc[r] = fmaf(hv.w, w3, acc[r]);
        }
    }

    const float b = b2[j];
#pragma unroll
    for (int r = 0; r < ROWS; ++r) {
        const float v = acc[r] + b;
        const int idx = r * DZc + j;
        if (MODE == 0) {
            ksum_s[idx] = v;
            zin_s[idx] = z_s[idx] + 0.5f * hstep * v;        // input for k2
        } else if (MODE == 1) {
            ksum_s[idx] += 2.f * v;
            zin_s[idx] = z_s[idx] + 0.5f * hstep * v;        // input for k3
        } else if (MODE == 2) {
            ksum_s[idx] += 2.f * v;
            zin_s[idx] = z_s[idx] + hstep * v;               // input for k4
        } else {
            const float ks = ksum_s[idx] + v;                // k1+2k2+2k3+k4
            z_s[idx] = z_s[idx] + (hstep * (1.f / 6.f)) * ks;
        }
    }
}

// ---------------------------------------------------------------------------
// Persistent per-row-block kernel: 128 CTAs x 8 rows, full 63-step scan local.
// ---------------------------------------------------------------------------
__global__ void __launch_bounds__(NTH, 1)
ode_kernel(const float* __restrict__ z0, const float* __restrict__ t,
           const float* __restrict__ x,  const float* __restrict__ W1,
           const float* __restrict__ Wx, const float* __restrict__ wt,
           const float* __restrict__ b1, const float* __restrict__ W2,
           const float* __restrict__ b2, float* __restrict__ out)
{
    extern __shared__ float sm[];
    float* z_s    = sm + OFF_Z;
    float* zin_s  = sm + OFF_ZIN;
    float* ksum_s = sm + OFF_KSUM;
    float* xb_s   = sm + OFF_XB;
    float* h_s    = sm + OFF_H;
    float* xs_s   = sm + OFF_XS;

    const int tid  = threadIdx.x;
    const int row0 = blockIdx.x * ROWS;

    // load z0 block
#pragma unroll
    for (int i = 0; i < (ROWS * DZc) / NTH; ++i) {
        const int idx = i * NTH + tid;
        const int r = idx / DZc, j = idx % DZc;
        z_s[idx] = z0[(row0 + r) * DZc + j];
    }
    __syncthreads();

    for (int step = 0; step < TT - 1; ++step) {
        const float t0 = __ldg(t + step);
        const float t1 = __ldg(t + step + 1);
        const float hstep = t1 - t0;

        // stage x[step] rows for this block
#pragma unroll
        for (int i = 0; i < (ROWS * DXc) / NTH; ++i) {
            const int idx = i * NTH + tid;
            const int r = idx / DXc, d = idx % DXc;
            xs_s[idx] = x[(step * BB + row0 + r) * DXc + d];
        }
        __syncthreads();

        gemm_xb(xs_s, Wx, b1, xb_s);          // xb = x@Wx + b1 (shared by 4 evals)
        __syncthreads();

        // k1 : f(z, t0)
        gemm1_tanh(z_s, xb_s, W1, wt, t0, h_s);
        __syncthreads();
        gemm2_update<0>(h_s, W2, b2, z_s, zin_s, ksum_s, hstep);
        __syncthreads();

        // k2 : f(z + h/2 k1, t0 + h/2)
        gemm1_tanh(zin_s, xb_s, W1, wt, t0 + 0.5f * hstep, h_s);
        __syncthreads();
        gemm2_update<1>(h_s, W2, b2, z_s, zin_s, ksum_s, hstep);
        __syncthreads();

        // k3 : f(z + h/2 k2, t0 + h/2)
        gemm1_tanh(zin_s, xb_s, W1, wt, t0 + 0.5f * hstep, h_s);
        __syncthreads();
        gemm2_update<2>(h_s, W2, b2, z_s, zin_s, ksum_s, hstep);
        __syncthreads();

        // k4 : f(z + h k3, t1), then z += h/6 (k1 + 2k2 + 2k3 + k4)
        gemm1_tanh(zin_s, xb_s, W1, wt, t1, h_s);
        __syncthreads();
        gemm2_update<3>(h_s, W2, b2, z_s, zin_s, ksum_s, hstep);
        __syncthreads();
    }

    // write z_final
#pragma unroll
    for (int i = 0; i < (ROWS * DZc) / NTH; ++i) {
        const int idx = i * NTH + tid;
        const int r = idx / DZc, j = idx % DZc;
        out[(row0 + r) * DZc + j] = z_s[idx];
    }
}

extern "C" void kernel_launch(void* const* d_in, const int* in_sizes, int n_in,
                              void* d_out, int out_size)
{
    const float* z0 = (const float*)d_in[0];
    const float* t  = (const float*)d_in[1];
    const float* x  = (const float*)d_in[2];
    const float* W1 = (const float*)d_in[3];
    const float* Wx = (const float*)d_in[4];
    const float* wt = (const float*)d_in[5];
    const float* b1 = (const float*)d_in[6];
    const float* W2 = (const float*)d_in[7];
    const float* b2 = (const float*)d_in[8];
    float* out = (float*)d_out;

    const size_t smem = SMEM_FLOATS * sizeof(float);   // ~90 KB
    cudaFuncSetAttribute(ode_kernel,
                         cudaFuncAttributeMaxDynamicSharedMemorySize, (int)smem);
    ode_kernel<<<NCTA, NTH, smem>>>(z0, t, x, W1, Wx, wt, b1, W2, b2, out);
}

// round 3
// speedup vs baseline: 1.1293x; 1.1293x over previous
#include <cuda_runtime.h>
#include <math.h>

// Problem constants
#define TT   64
#define BB   1024
#define DZc  256
#define DXc  64
#define DHc  1024

#define ROWS 8                 // batch rows per CTA
#define NCTA (BB / ROWS)       // 128 CTAs
#define NTH  512               // threads per CTA (16 warps)

// Dynamic shared memory layout (in floats)
#define OFF_Z    0
#define OFF_ZIN  (OFF_Z    + ROWS * DZc)        // 2048
#define OFF_KSUM (OFF_ZIN  + ROWS * DZc)        // 4096
#define OFF_XB   (OFF_KSUM + ROWS * DZc)        // 6144
#define OFF_H    (OFF_XB   + ROWS * DHc)        // 14336
#define OFF_P    (OFF_H    + ROWS * DHc)        // 22528
#define OFF_XS   (OFF_P    + ROWS * DHc)        // 30720
#define SMEM_FLOATS (OFF_XS + ROWS * DXc)       // 31232 floats = 122 KB

// ---------------------------------------------------------------------------
// fast tanh: tanh(|x|) = (1-e)/(1+e), e = exp(-2|x|).  ~1e-6 abs error.
// 2 MUFU (EX2, RCP) + a few ALU, vs ~35-instr libdevice tanhf.
// ---------------------------------------------------------------------------
__device__ __forceinline__ float fast_tanh(float x)
{
    const float ax = fabsf(x);
    const float e  = __expf(-2.0f * ax);
    const float y  = (1.0f - e) * __fdividef(1.0f, 1.0f + e);
    return copysignf(y, x);
}

// ---------------------------------------------------------------------------
// GEMM1 main (split-K): partial[8 rows][4 cols] over half the K range.
// half 0 -> h_s, half 1 -> p_s.  W streamed float4 (coalesced), z broadcast LDS.
// KTOT = DZc (W = W1, in = zin_s, stride DZc) or DXc (W = Wx, in = xs_s).
// ---------------------------------------------------------------------------
template <int KTOT, int INSTRIDE>
__device__ __forceinline__ void gemm1_main(
    const float* in_s, const float* __restrict__ W, float* out_part)
{
    const int lane = threadIdx.x & 255;
    const int half = threadIdx.x >> 8;
    const int c0   = lane * 4;
    const int kb   = half * (KTOT / 2);

    float4 acc[ROWS];
#pragma unroll
    for (int r = 0; r < ROWS; ++r) acc[r] = make_float4(0.f, 0.f, 0.f, 0.f);

#pragma unroll 2
    for (int k = kb; k < kb + KTOT / 2; k += 4) {
        const float4 w0 = *(const float4*)(W + (k + 0) * DHc + c0);
        const float4 w1 = *(const float4*)(W + (k + 1) * DHc + c0);
        const float4 w2 = *(const float4*)(W + (k + 2) * DHc + c0);
        const float4 w3 = *(const float4*)(W + (k + 3) * DHc + c0);
#pragma unroll
        for (int r = 0; r < ROWS; ++r) {
            const float4 zv = *(const float4*)(in_s + r * INSTRIDE + k);
            acc[r].x = fmaf(zv.x, w0.x, acc[r].x);
            acc[r].y = fmaf(zv.x, w0.y, acc[r].y);
            acc[r].z = fmaf(zv.x, w0.z, acc[r].z);
            acc[r].w = fmaf(zv.x, w0.w, acc[r].w);
            acc[r].x = fmaf(zv.y, w1.x, acc[r].x);
            acc[r].y = fmaf(zv.y, w1.y, acc[r].y);
            acc[r].z = fmaf(zv.y, w1.z, acc[r].z);
            acc[r].w = fmaf(zv.y, w1.w, acc[r].w);
            acc[r].x = fmaf(zv.z, w2.x, acc[r].x);
            acc[r].y = fmaf(zv.z, w2.y, acc[r].y);
            acc[r].z = fmaf(zv.z, w2.z, acc[r].z);
            acc[r].w = fmaf(zv.z, w2.w, acc[r].w);
            acc[r].x = fmaf(zv.w, w3.x, acc[r].x);
            acc[r].y = fmaf(zv.w, w3.y, acc[r].y);
            acc[r].z = fmaf(zv.w, w3.z, acc[r].z);
            acc[r].w = fmaf(zv.w, w3.w, acc[r].w);
        }
    }

#pragma unroll
    for (int r = 0; r < ROWS; ++r)
        *(float4*)(out_part + r * DHc + c0) = acc[r];
}

// ---------------------------------------------------------------------------
// Persistent kernel
// ---------------------------------------------------------------------------
__global__ void __launch_bounds__(NTH, 1)
ode_kernel(const float* __restrict__ z0, const float* __restrict__ t,
           const float* __restrict__ x,  const float* __restrict__ W1,
           const float* __restrict__ Wx, const float* __restrict__ wt,
           const float* __restrict__ b1, const float* __restrict__ W2,
           const float* __restrict__ b2, float* __restrict__ out)
{
    extern __shared__ float sm[];
    float* z_s    = sm + OFF_Z;
    float* zin_s  = sm + OFF_ZIN;
    float* ksum_s = sm + OFF_KSUM;
    float* xb_s   = sm + OFF_XB;
    float* h_s    = sm + OFF_H;
    float* p_s    = sm + OFF_P;
    float* xs_s   = sm + OFF_XS;
    float* pa_s   = p_s;                    // GEMM2 partials (reuse p region)
    float* pb_s   = p_s + ROWS * DZc;

    const int tid  = threadIdx.x;
    const int half = tid >> 8;
    const int row0 = blockIdx.x * ROWS;

    // load z0 block (2048 floats / 512 threads)
#pragma unroll
    for (int i = 0; i < (ROWS * DZc) / NTH; ++i)
        z_s[i * NTH + tid] = z0[row0 * DZc + i * NTH + tid];
    __syncthreads();

    for (int step = 0; step < TT - 1; ++step) {
        const float t0 = __ldg(t + step);
        const float t1 = __ldg(t + step + 1);
        const float hstep = t1 - t0;
        const float tmid  = t0 + 0.5f * hstep;

        // stage x[step] rows (512 floats)
        xs_s[tid] = x[(step * BB + row0) * DXc + tid];
        __syncthreads();

        // ---- xb = x @ Wx + b1 (split-K over DX=64) ----
        gemm1_main<DXc, DXc>(xs_s, Wx, half ? p_s : h_s);
        __syncthreads();
#pragma unroll
        for (int i = 0; i < 4; ++i) {                      // combine by all threads
            const int pos = tid + i * NTH;                 // float4 index [0,2048)
            const int off = (pos >> 8) * DHc + (pos & 255) * 4;
            const float4 a  = *(const float4*)(h_s + off);
            const float4 b  = *(const float4*)(p_s + off);
            const float4 bb = *(const float4*)(b1 + (pos & 255) * 4);
            float4 v;
            v.x = a.x + b.x + bb.x;  v.y = a.y + b.y + bb.y;
            v.z = a.z + b.z + bb.z;  v.w = a.w + b.w + bb.w;
            *(float4*)(xb_s + off) = v;
        }
        __syncthreads();

        // ---- 4 RK4 sub-evaluations ----
#pragma unroll 1
        for (int sub = 0; sub < 4; ++sub) {
            const float ts = (sub == 0) ? t0 : (sub == 3 ? t1 : tmid);
            const float* zi = (sub == 0) ? z_s : zin_s;

            // GEMM1 main: partials into h_s (half0) / p_s (half1)
            gemm1_main<DZc, DZc>(zi, W1, half ? p_s : h_s);
            __syncthreads();

            // GEMM1 combine + tanh (all threads, in-place into h_s)
#pragma unroll
            for (int i = 0; i < 4; ++i) {
                const int pos = tid + i * NTH;
                const int c   = (pos & 255) * 4;
                const int off = (pos >> 8) * DHc + c;
                const float4 a   = *(const float4*)(h_s + off);
                const float4 b   = *(const float4*)(p_s + off);
                const float4 xbv = *(const float4*)(xb_s + off);
                const float4 wtv = *(const float4*)(wt + c);
                float4 hv;
                hv.x = fast_tanh(a.x + b.x + xbv.x + ts * wtv.x);
                hv.y = fast_tanh(a.y + b.y + xbv.y + ts * wtv.y);
                hv.z = fast_tanh(a.z + b.z + xbv.z + ts * wtv.z);
                hv.w = fast_tanh(a.w + b.w + xbv.w + ts * wtv.w);
                *(float4*)(h_s + off) = hv;
            }
            __syncthreads();

            // GEMM2 main (split-K over DH): acc[8 rows] for col j, k-half
            {
                const int j  = tid & 255;
                const int kb = half * (DHc / 2);
                float acc[ROWS];
#pragma unroll
                for (int r = 0; r < ROWS; ++r) acc[r] = 0.f;
#pragma unroll 2
                for (int k = kb; k < kb + DHc / 2; k += 4) {
                    const float w0 = __ldg(W2 + (k + 0) * DZc + j);
                    const float w1 = __ldg(W2 + (k + 1) * DZc + j);
                    const float w2 = __ldg(W2 + (k + 2) * DZc + j);
                    const float w3 = __ldg(W2 + (k + 3) * DZc + j);
#pragma unroll
                    for (int r = 0; r < ROWS; ++r) {
                        const float4 hv = *(const float4*)(h_s + r * DHc + k);
                        acc[r] = fmaf(hv.x, w0, acc[r]);
                        acc[r] = fmaf(hv.y, w1, acc[r]);
                        acc[r] = fmaf(hv.z, w2, acc[r]);
                        acc[r] = fmaf(hv.w, w3, acc[r]);
                    }
                }
                float* dst = half ? pb_s : pa_s;
#pragma unroll
                for (int r = 0; r < ROWS; ++r) dst[r * DZc + j] = acc[r];
            }
            __syncthreads();

            // GEMM2 combine + RK4 update (all threads, 4 elements each)
#pragma unroll
            for (int i = 0; i < 4; ++i) {
                const int idx = tid + i * NTH;             // == r*DZc + j
                const float v = pa_s[idx] + pb_s[idx] + __ldg(b2 + (idx & 255));
                if (sub == 0) {
                    ksum_s[idx] = v;
                    zin_s[idx]  = z_s[idx] + 0.5f * hstep * v;
                } else if (sub == 1) {
                    ksum_s[idx] += 2.f * v;
                    zin_s[idx]  = z_s[idx] + 0.5f * hstep * v;
                } else if (sub == 2) {
                    ksum_s[idx] += 2.f * v;
                    zin_s[idx]  = z_s[idx] + hstep * v;
                } else {
                    z_s[idx] = z_s[idx] + (hstep * (1.f / 6.f)) * (ksum_s[idx] + v);
                }
            }
            __syncthreads();
        }
    }

    // write z_final
#pragma unroll
    for (int i = 0; i < (ROWS * DZc) / NTH; ++i)
        out[row0 * DZc + i * NTH + tid] = z_s[i * NTH + tid];
}

extern "C" void kernel_launch(void* const* d_in, const int* in_sizes, int n_in,
                              void* d_out, int out_size)
{
    const float* z0 = (const float*)d_in[0];
    const float* t  = (const float*)d_in[1];
    const float* x  = (const float*)d_in[2];
    const float* W1 = (const float*)d_in[3];
    const float* Wx = (const float*)d_in[4];
    const float* wt = (const float*)d_in[5];
    const float* b1 = (const float*)d_in[6];
    const float* W2 = (const float*)d_in[7];
    const float* b2 = (const float*)d_in[8];
    float* out = (float*)d_out;

    const size_t smem = SMEM_FLOATS * sizeof(float);   // ~122 KB
    cudaFuncSetAttribute(ode_kernel,
                         cudaFuncAttributeMaxDynamicSharedMemorySize, (int)smem);
    ode_kernel<<<NCTA, NTH, smem>>>(z0, t, x, W1, Wx, wt, b1, W2, b2, out);
}

// round 4
// speedup vs baseline: 1.1819x; 1.0466x over previous
#include <cuda_runtime.h>
#include <math.h>

// Problem constants
#define TT   64
#define BB   1024
#define DZc  256
#define DXc  64
#define DHc  1024

#define ROWS 8                 // batch rows per CTA
#define NCTA (BB / ROWS)       // 128 CTAs
#define NTH  512               // threads per CTA (16 warps)

// Dynamic shared memory layout (in floats)
#define OFF_Z     0
#define OFF_KSUM  (OFF_Z     + ROWS * DZc)       // 2048
#define OFF_XB    (OFF_KSUM  + ROWS * DZc)       // 4096
#define OFF_H     (OFF_XB    + ROWS * DHc)       // 12288
#define OFF_P     (OFF_H     + ROWS * DHc)       // 20480
#define OFF_ZD    (OFF_P     + ROWS * DHc)       // 28672  z duplicated pairs
#define OFF_ZIND  (OFF_ZD    + 2 * ROWS * DZc)   // 32768  zin duplicated pairs
#define OFF_XSD   (OFF_ZIND  + 2 * ROWS * DZc)   // 36864  x duplicated pairs
#define SMEM_FLOATS (OFF_XSD + 2 * ROWS * DXc)   // 37888 floats = 148 KB

typedef unsigned long long u64;

// packed f32x2 FMA: acc(2 lanes) += a * b   (one issue slot, 2 FMAs)
__device__ __forceinline__ void fma2(u64& acc, u64 a, u64 b)
{
    asm("fma.rn.f32x2 %0, %1, %2, %0;" : "+l"(acc) : "l"(a), "l"(b));
}
__device__ __forceinline__ u64 pack2(float lo, float hi)
{
    u64 p;
    asm("mov.b64 %0, {%1, %2};" : "=l"(p) : "f"(lo), "f"(hi));
    return p;
}
__device__ __forceinline__ float2 unpack2(u64 p)
{
    float2 v;
    asm("mov.b64 {%0, %1}, %2;" : "=f"(v.x), "=f"(v.y) : "l"(p));
    return v;
}

// ---------------------------------------------------------------------------
// fast tanh: tanh(|x|) = (1-e)/(1+e), e = exp(-2|x|).  ~1e-6 abs error.
// ---------------------------------------------------------------------------
__device__ __forceinline__ float fast_tanh(float x)
{
    const float ax = fabsf(x);
    const float e  = __expf(-2.0f * ax);
    const float y  = (1.0f - e) * __fdividef(1.0f, 1.0f + e);
    return copysignf(y, x);
}

// ---------------------------------------------------------------------------
// GEMM1 main (split-K, f32x2 col-packed): partials for 8 rows x 4 cols.
// indup_s holds duplicated pairs (v,v): row stride 2*KTOT floats.
// W float4 loads give (c0,c1),(c2,c3) pairs for free (little-endian u64s).
// ---------------------------------------------------------------------------
template <int KTOT>
__device__ __forceinline__ void gemm1_main(
    const float* indup_s, const float* __restrict__ W, float* out_part)
{
    const int lane = threadIdx.x & 255;
    const int half = threadIdx.x >> 8;
    const int c0   = lane * 4;
    const int kb   = half * (KTOT / 2);

    u64 a0[ROWS], a1[ROWS];
#pragma unroll
    for (int r = 0; r < ROWS; ++r) { a0[r] = 0ull; a1[r] = 0ull; }

#pragma unroll 2
    for (int k = kb; k < kb + KTOT / 2; k += 2) {
        const ulonglong2 w0 = *(const ulonglong2*)(W + (k + 0) * DHc + c0);
        const ulonglong2 w1 = *(const ulonglong2*)(W + (k + 1) * DHc + c0);
#pragma unroll
        for (int r = 0; r < ROWS; ++r) {
            // (z_k,z_k) and (z_{k+1},z_{k+1}) duplicated pairs, one LDS.128
            const ulonglong2 zp = *(const ulonglong2*)(indup_s + r * 2 * KTOT + 2 * k);
            fma2(a0[r], zp.x, w0.x);
            fma2(a1[r], zp.x, w0.y);
            fma2(a0[r], zp.y, w1.x);
            fma2(a1[r], zp.y, w1.y);
        }
    }

#pragma unroll
    for (int r = 0; r < ROWS; ++r) {
        ulonglong2 v; v.x = a0[r]; v.y = a1[r];
        *(ulonglong2*)(out_part + r * DHc + c0) = v;
    }
}

// ---------------------------------------------------------------------------
// Persistent kernel
// ---------------------------------------------------------------------------
__global__ void __launch_bounds__(NTH, 1)
ode_kernel(const float* __restrict__ z0, const float* __restrict__ t,
           const float* __restrict__ x,  const float* __restrict__ W1,
           const float* __restrict__ Wx, const float* __restrict__ wt,
           const float* __restrict__ b1, const float* __restrict__ W2,
           const float* __restrict__ b2, float* __restrict__ out)
{
    extern __shared__ float sm[];
    float* z_s    = sm + OFF_Z;
    float* ksum_s = sm + OFF_KSUM;
    float* xb_s   = sm + OFF_XB;
    float* h_s    = sm + OFF_H;
    float* p_s    = sm + OFF_P;
    float* zd_s   = sm + OFF_ZD;     // z duplicated pairs   [r][2k]
    float* zind_s = sm + OFF_ZIND;   // zin duplicated pairs [r][2k]
    float* xsd_s  = sm + OFF_XSD;    // x duplicated pairs   [r][2d]
    float* pa_s   = p_s;             // GEMM2 partials (reuse p region)
    float* pb_s   = p_s + ROWS * DZc;

    const int tid  = threadIdx.x;
    const int half = tid >> 8;
    const int row0 = blockIdx.x * ROWS;

    // load z0 block (2048 floats / 512 threads) into z_s and zd_s
#pragma unroll
    for (int i = 0; i < (ROWS * DZc) / NTH; ++i) {
        const int idx = i * NTH + tid;                 // r*DZc + j
        const float v = z0[row0 * DZc + idx];
        z_s[idx] = v;
        *(float2*)(zd_s + ((idx >> 8) << 9) + ((idx & 255) << 1)) = make_float2(v, v);
    }
    __syncthreads();

    for (int step = 0; step < TT - 1; ++step) {
        const float t0 = __ldg(t + step);
        const float t1 = __ldg(t + step + 1);
        const float hstep = t1 - t0;
        const float tmid  = t0 + 0.5f * hstep;

        // stage x[step] rows (512 floats) as duplicated pairs
        {
            const float v = x[(step * BB + row0) * DXc + tid];   // r = tid>>6, d = tid&63
            *(float2*)(xsd_s + ((tid >> 6) << 7) + ((tid & 63) << 1)) = make_float2(v, v);
        }
        __syncthreads();

        // ---- xb = x @ Wx + b1 (split-K over DX=64) ----
        gemm1_main<DXc>(xsd_s, Wx, half ? p_s : h_s);
        __syncthreads();
#pragma unroll
        for (int i = 0; i < 4; ++i) {                      // combine by all threads
            const int pos = tid + i * NTH;                 // float4 index [0,2048)
            const int off = (pos >> 8) * DHc + (pos & 255) * 4;
            const float4 a  = *(const float4*)(h_s + off);
            const float4 b  = *(const float4*)(p_s + off);
            const float4 bb = *(const float4*)(b1 + (pos & 255) * 4);
            float4 v;
            v.x = a.x + b.x + bb.x;  v.y = a.y + b.y + bb.y;
            v.z = a.z + b.z + bb.z;  v.w = a.w + b.w + bb.w;
            *(float4*)(xb_s + off) = v;
        }
        __syncthreads();

        // ---- 4 RK4 sub-evaluations ----
#pragma unroll 1
        for (int sub = 0; sub < 4; ++sub) {
            const float ts = (sub == 0) ? t0 : (sub == 3 ? t1 : tmid);
            const float* zi = (sub == 0) ? zd_s : zind_s;

            // GEMM1 main: partials into h_s (half0) / p_s (half1)
            gemm1_main<DZc>(zi, W1, half ? p_s : h_s);
            __syncthreads();

            // GEMM1 combine + tanh (all threads, in-place into h_s)
#pragma unroll
            for (int i = 0; i < 4; ++i) {
                const int pos = tid + i * NTH;
                const int c   = (pos & 255) * 4;
                const int off = (pos >> 8) * DHc + c;
                const float4 a   = *(const float4*)(h_s + off);
                const float4 b   = *(const float4*)(p_s + off);
                const float4 xbv = *(const float4*)(xb_s + off);
                const float4 wtv = *(const float4*)(wt + c);
                float4 hv;
                hv.x = fast_tanh(a.x + b.x + xbv.x + ts * wtv.x);
                hv.y = fast_tanh(a.y + b.y + xbv.y + ts * wtv.y);
                hv.z = fast_tanh(a.z + b.z + xbv.z + ts * wtv.z);
                hv.w = fast_tanh(a.w + b.w + xbv.w + ts * wtv.w);
                *(float4*)(h_s + off) = hv;
            }
            __syncthreads();

            // GEMM2 main (split-K over DH, f32x2 k-packed): col j, 8 rows
            {
                const int j  = tid & 255;
                const int kb = half * (DHc / 2);
                u64 acc2[ROWS];
#pragma unroll
                for (int r = 0; r < ROWS; ++r) acc2[r] = 0ull;
#pragma unroll 2
                for (int k = kb; k < kb + DHc / 2; k += 4) {
                    const float w0 = __ldg(W2 + (k + 0) * DZc + j);
                    const float w1 = __ldg(W2 + (k + 1) * DZc + j);
                    const float w2 = __ldg(W2 + (k + 2) * DZc + j);
                    const float w3 = __ldg(W2 + (k + 3) * DZc + j);
                    const u64 wp01 = pack2(w0, w1);
                    const u64 wp23 = pack2(w2, w3);
#pragma unroll
                    for (int r = 0; r < ROWS; ++r) {
                        // (h_k,h_{k+1}) and (h_{k+2},h_{k+3}) free pairs
                        const ulonglong2 hp = *(const ulonglong2*)(h_s + r * DHc + k);
                        fma2(acc2[r], hp.x, wp01);
                        fma2(acc2[r], hp.y, wp23);
                    }
                }
                float* dst = half ? pb_s : pa_s;
#pragma unroll
                for (int r = 0; r < ROWS; ++r) {
                    const float2 v = unpack2(acc2[r]);
                    dst[r * DZc + j] = v.x + v.y;
                }
            }
            __syncthreads();

            // GEMM2 combine + RK4 update (all threads, 4 elements each)
#pragma unroll
            for (int i = 0; i < 4; ++i) {
                const int idx = tid + i * NTH;             // == r*DZc + j
                const int doff = ((idx >> 8) << 9) + ((idx & 255) << 1);
                const float v = pa_s[idx] + pb_s[idx] + __ldg(b2 + (idx & 255));
                if (sub == 0) {
                    ksum_s[idx] = v;
                    const float zi = z_s[idx] + 0.5f * hstep * v;
                    *(float2*)(zind_s + doff) = make_float2(zi, zi);
                } else if (sub == 1) {
                    ksum_s[idx] += 2.f * v;
                    const float zi = z_s[idx] + 0.5f * hstep * v;
                    *(float2*)(zind_s + doff) = make_float2(zi, zi);
                } else if (sub == 2) {
                    ksum_s[idx] += 2.f * v;
                    const float zi = z_s[idx] + hstep * v;
                    *(float2*)(zind_s + doff) = make_float2(zi, zi);
                } else {
                    const float nz = z_s[idx] + (hstep * (1.f / 6.f)) * (ksum_s[idx] + v);
                    z_s[idx] = nz;
                    *(float2*)(zd_s + doff) = make_float2(nz, nz);
                }
            }
            __syncthreads();
        }
    }

    // write z_final
#pragma unroll
    for (int i = 0; i < (ROWS * DZc) / NTH; ++i)
        out[row0 * DZc + i * NTH + tid] = z_s[i * NTH + tid];
}

extern "C" void kernel_launch(void* const* d_in, const int* in_sizes, int n_in,
                              void* d_out, int out_size)
{
    const float* z0 = (const float*)d_in[0];
    const float* t  = (const float*)d_in[1];
    const float* x  = (const float*)d_in[2];
    const float* W1 = (const float*)d_in[3];
    const float* Wx = (const float*)d_in[4];
    const float* wt = (const float*)d_in[5];
    const float* b1 = (const float*)d_in[6];
    const float* W2 = (const float*)d_in[7];
    const float* b2 = (const float*)d_in[8];
    float* out = (float*)d_out;

    const size_t smem = SMEM_FLOATS * sizeof(float);   // ~148 KB
    cudaFuncSetAttribute(ode_kernel,
                         cudaFuncAttributeMaxDynamicSharedMemorySize, (int)smem);
    ode_kernel<<<NCTA, NTH, smem>>>(z0, t, x, W1, Wx, wt, b1, W2, b2, out);
}

// round 5
// speedup vs baseline: 1.3708x; 1.1599x over previous
#include <cuda_runtime.h>
#include <math.h>

// Problem constants
#define TT   64
#define BB   1024
#define DZc  256
#define DXc  64
#define DHc  1024

#define ROWS 8                 // batch rows per CTA
#define NCTA (BB / ROWS)       // 128 CTAs
#define NTH  512               // threads per CTA (16 warps)

// Dynamic shared memory layout (in floats)
#define OFF_Z     0                              // z            2048
#define OFF_KSUM  (OFF_Z    + ROWS * DZc)        // ksum         2048
#define OFF_XB    (OFF_KSUM + ROWS * DZc)        // xb           8192
#define OFF_HD    (OFF_XB   + ROWS * DHc)        // h duplicated 16384
#define OFF_PART  (OFF_HD   + 2 * ROWS * DHc)    // partials     16384
#define OFF_ZD    (OFF_PART + 2 * ROWS * DHc)    // z dup        4096
#define OFF_ZIND  (OFF_ZD   + 2 * ROWS * DZc)    // zin dup      4096
#define OFF_XSD   (OFF_ZIND + 2 * ROWS * DZc)    // x dup        1024
#define SMEM_FLOATS (OFF_XSD + 2 * ROWS * DXc)   // 54272 floats = 212 KB

typedef unsigned long long u64;

// packed f32x2 FMA: acc(2 lanes) += a * b   (one issue slot, 2 FMAs)
__device__ __forceinline__ void fma2(u64& acc, u64 a, u64 b)
{
    asm("fma.rn.f32x2 %0, %1, %2, %0;" : "+l"(acc) : "l"(a), "l"(b));
}
__device__ __forceinline__ float2 unpack2(u64 p)
{
    float2 v;
    asm("mov.b64 {%0, %1}, %2;" : "=f"(v.x), "=f"(v.y) : "l"(p));
    return v;
}

// fast tanh: tanh(|x|) = (1-e)/(1+e), e = exp(-2|x|).  ~1e-6 abs error.
__device__ __forceinline__ float fast_tanh(float x)
{
    const float ax = fabsf(x);
    const float e  = __expf(-2.0f * ax);
    const float y  = (1.0f - e) * __fdividef(1.0f, 1.0f + e);
    return copysignf(y, x);
}

// ---------------------------------------------------------------------------
// GEMM1 main (split-K 2-way, f32x2 col-packed): partials for 8 rows x 4 cols.
// indup_s holds duplicated pairs (v,v): row stride 2*KTOT floats.
// ---------------------------------------------------------------------------
template <int KTOT>
__device__ __forceinline__ void gemm1_main(
    const float* indup_s, const float* __restrict__ W, float* out_part)
{
    const int lane = threadIdx.x & 255;
    const int half = threadIdx.x >> 8;
    const int c0   = lane * 4;
    const int kb   = half * (KTOT / 2);

    u64 a0[ROWS], a1[ROWS];
#pragma unroll
    for (int r = 0; r < ROWS; ++r) { a0[r] = 0ull; a1[r] = 0ull; }

#pragma unroll 2
    for (int k = kb; k < kb + KTOT / 2; k += 2) {
        const ulonglong2 w0 = *(const ulonglong2*)(W + (k + 0) * DHc + c0);
        const ulonglong2 w1 = *(const ulonglong2*)(W + (k + 1) * DHc + c0);
#pragma unroll
        for (int r = 0; r < ROWS; ++r) {
            const ulonglong2 zp = *(const ulonglong2*)(indup_s + r * 2 * KTOT + 2 * k);
            fma2(a0[r], zp.x, w0.x);
            fma2(a1[r], zp.x, w0.y);
            fma2(a0[r], zp.y, w1.x);
            fma2(a1[r], zp.y, w1.y);
        }
    }

#pragma unroll
    for (int r = 0; r < ROWS; ++r) {
        ulonglong2 v; v.x = a0[r]; v.y = a1[r];
        *(ulonglong2*)(out_part + r * DHc + c0) = v;
    }
}

// ---------------------------------------------------------------------------
// Persistent kernel
// ---------------------------------------------------------------------------
__global__ void __launch_bounds__(NTH, 1)
ode_kernel(const float* __restrict__ z0, const float* __restrict__ t,
           const float* __restrict__ x,  const float* __restrict__ W1,
           const float* __restrict__ Wx, const float* __restrict__ wt,
           const float* __restrict__ b1, const float* __restrict__ W2,
           const float* __restrict__ b2, float* __restrict__ out)
{
    extern __shared__ float sm[];
    float* z_s    = sm + OFF_Z;
    float* ksum_s = sm + OFF_KSUM;
    float* xb_s   = sm + OFF_XB;
    float* hd_s   = sm + OFF_HD;     // h duplicated pairs [r][2k], stride 2048
    float* part_s = sm + OFF_PART;   // GEMM1: 2 halves of [r][c]; GEMM2: 8 segs of [r][j]
    float* zd_s   = sm + OFF_ZD;     // z duplicated pairs   [r][2j], stride 512
    float* zind_s = sm + OFF_ZIND;   // zin duplicated pairs [r][2j]
    float* xsd_s  = sm + OFF_XSD;    // x duplicated pairs   [r][2d], stride 128
    float* pa_s   = part_s;                  // GEMM1 half-0 partial [r*DHc + c]
    float* pb_s   = part_s + ROWS * DHc;     // GEMM1 half-1 partial

    const int tid  = threadIdx.x;
    const int half = tid >> 8;
    const int row0 = blockIdx.x * ROWS;

    // load z0 block (2048 floats / 512 threads) into z_s and zd_s
#pragma unroll
    for (int i = 0; i < (ROWS * DZc) / NTH; ++i) {
        const int idx = i * NTH + tid;                 // r*DZc + j
        const float v = z0[row0 * DZc + idx];
        z_s[idx] = v;
        *(float2*)(zd_s + ((idx >> 8) << 9) + ((idx & 255) << 1)) = make_float2(v, v);
    }
    __syncthreads();

    for (int step = 0; step < TT - 1; ++step) {
        const float t0 = __ldg(t + step);
        const float t1 = __ldg(t + step + 1);
        const float hstep = t1 - t0;
        const float tmid  = t0 + 0.5f * hstep;

        // stage x[step] rows (512 floats) as duplicated pairs
        {
            const float v = x[(step * BB + row0) * DXc + tid];   // r = tid>>6, d = tid&63
            *(float2*)(xsd_s + ((tid >> 6) << 7) + ((tid & 63) << 1)) = make_float2(v, v);
        }
        __syncthreads();

        // ---- xb = x @ Wx + b1 (split-K over DX=64) ----
        gemm1_main<DXc>(xsd_s, Wx, half ? pb_s : pa_s);
        __syncthreads();
#pragma unroll
        for (int i = 0; i < 4; ++i) {
            const int pos = tid + i * NTH;                 // float4 index [0,2048)
            const int off = (pos >> 8) * DHc + (pos & 255) * 4;
            const float4 a  = *(const float4*)(pa_s + off);
            const float4 b  = *(const float4*)(pb_s + off);
            const float4 bb = *(const float4*)(b1 + (pos & 255) * 4);
            float4 v;
            v.x = a.x + b.x + bb.x;  v.y = a.y + b.y + bb.y;
            v.z = a.z + b.z + bb.z;  v.w = a.w + b.w + bb.w;
            *(float4*)(xb_s + off) = v;
        }
        __syncthreads();

        // ---- 4 RK4 sub-evaluations ----
#pragma unroll 1
        for (int sub = 0; sub < 4; ++sub) {
            const float ts = (sub == 0) ? t0 : (sub == 3 ? t1 : tmid);
            const float* zi = (sub == 0) ? zd_s : zind_s;

            // GEMM1 main: partials into pa (half0) / pb (half1)
            gemm1_main<DZc>(zi, W1, half ? pb_s : pa_s);
            __syncthreads();

            // GEMM1 combine + tanh -> h duplicated (all threads)
#pragma unroll
            for (int i = 0; i < 4; ++i) {
                const int pos = tid + i * NTH;
                const int c   = (pos & 255) * 4;
                const int r   = pos >> 8;
                const int off = r * DHc + c;
                const float4 a   = *(const float4*)(pa_s + off);
                const float4 b   = *(const float4*)(pb_s + off);
                const float4 xbv = *(const float4*)(xb_s + off);
                const float4 wtv = *(const float4*)(wt + c);
                const float h0 = fast_tanh(a.x + b.x + xbv.x + ts * wtv.x);
                const float h1 = fast_tanh(a.y + b.y + xbv.y + ts * wtv.y);
                const float h2 = fast_tanh(a.z + b.z + xbv.z + ts * wtv.z);
                const float h3 = fast_tanh(a.w + b.w + xbv.w + ts * wtv.w);
                float* dst = hd_s + r * (2 * DHc) + 2 * c;
                *(float4*)(dst)     = make_float4(h0, h0, h1, h1);
                *(float4*)(dst + 4) = make_float4(h2, h2, h3, h3);
            }
            __syncthreads();

            // GEMM2 main (split-K 8-way, f32x2 col-packed):
            // thread = (col-group cg of 4 cols, k-segment of 128 k's)
            {
                const int cg   = tid & 63;
                const int kseg = tid >> 6;
                const int j0   = cg * 4;
                const int kb   = kseg * (DHc / 8);
                u64 a01[ROWS], a23[ROWS];
#pragma unroll
                for (int r = 0; r < ROWS; ++r) { a01[r] = 0ull; a23[r] = 0ull; }

#pragma unroll 2
                for (int k = kb; k < kb + DHc / 8; k += 2) {
                    const ulonglong2 wA = *(const ulonglong2*)(W2 + (k + 0) * DZc + j0);
                    const ulonglong2 wB = *(const ulonglong2*)(W2 + (k + 1) * DZc + j0);
#pragma unroll
                    for (int r = 0; r < ROWS; ++r) {
                        // (h_k,h_k),(h_{k+1},h_{k+1}) duplicated pairs, one LDS.128
                        const ulonglong2 hp = *(const ulonglong2*)(hd_s + r * (2 * DHc) + 2 * k);
                        fma2(a01[r], hp.x, wA.x);
                        fma2(a23[r], hp.x, wA.y);
                        fma2(a01[r], hp.y, wB.x);
                        fma2(a23[r], hp.y, wB.y);
                    }
                }
                // reduce pair lanes and store partial [kseg][r][j0..j0+3]
#pragma unroll
                for (int r = 0; r < ROWS; ++r) {
                    const float2 v01 = unpack2(a01[r]);
                    const float2 v23 = unpack2(a23[r]);
                    // note: lanes hold (j0,j1) and (j2,j3) column values (not to sum!)
                    *(float4*)(part_s + kseg * (ROWS * DZc) + r * DZc + j0) =
                        make_float4(v01.x, v01.y, v23.x, v23.y);
                }
            }
            __syncthreads();

            // combine 8 partials + RK4 update (thread owns 4 outputs: row r, cols j0..j0+3)
            {
                const int r  = tid >> 6;
                const int j0 = (tid & 63) * 4;
                const int base = r * DZc + j0;
                float4 s = *(const float4*)(part_s + base);
#pragma unroll
                for (int seg = 1; seg < 8; ++seg) {
                    const float4 p = *(const float4*)(part_s + seg * (ROWS * DZc) + base);
                    s.x += p.x; s.y += p.y; s.z += p.z; s.w += p.w;
                }
                const float4 bb = *(const float4*)(b2 + j0);
                const float v0 = s.x + bb.x, v1 = s.y + bb.y;
                const float v2 = s.z + bb.z, v3 = s.w + bb.w;

                const float4 zv = *(const float4*)(z_s + base);
                float* dup = zind_s + r * (2 * DZc) + 2 * j0;

                if (sub == 0) {
                    *(float4*)(ksum_s + base) = make_float4(v0, v1, v2, v3);
                    const float c = 0.5f * hstep;
                    const float n0 = zv.x + c * v0, n1 = zv.y + c * v1;
                    const float n2 = zv.z + c * v2, n3 = zv.w + c * v3;
                    *(float4*)(dup)     = make_float4(n0, n0, n1, n1);
                    *(float4*)(dup + 4) = make_float4(n2, n2, n3, n3);
                } else if (sub == 1 || sub == 2) {
                    float4 ks = *(const float4*)(ksum_s + base);
                    ks.x += 2.f * v0; ks.y += 2.f * v1;
                    ks.z += 2.f * v2; ks.w += 2.f * v3;
                    *(float4*)(ksum_s + base) = ks;
                    const float c = (sub == 1) ? 0.5f * hstep : hstep;
                    const float n0 = zv.x + c * v0, n1 = zv.y + c * v1;
                    const float n2 = zv.z + c * v2, n3 = zv.w + c * v3;
                    *(float4*)(dup)     = make_float4(n0, n0, n1, n1);
                    *(float4*)(dup + 4) = make_float4(n2, n2, n3, n3);
                } else {
                    const float4 ks = *(const float4*)(ksum_s + base);
                    const float c = hstep * (1.f / 6.f);
                    const float n0 = zv.x + c * (ks.x + v0);
                    const float n1 = zv.y + c * (ks.y + v1);
                    const float n2 = zv.z + c * (ks.z + v2);
                    const float n3 = zv.w + c * (ks.w + v3);
                    *(float4*)(z_s + base) = make_float4(n0, n1, n2, n3);
                    float* zdup = zd_s + r * (2 * DZc) + 2 * j0;
                    *(float4*)(zdup)     = make_float4(n0, n0, n1, n1);
                    *(float4*)(zdup + 4) = make_float4(n2, n2, n3, n3);
                }
            }
            __syncthreads();
        }
    }

    // write z_final
#pragma unroll
    for (int i = 0; i < (ROWS * DZc) / NTH; ++i)
        out[row0 * DZc + i * NTH + tid] = z_s[i * NTH + tid];
}

extern "C" void kernel_launch(void* const* d_in, const int* in_sizes, int n_in,
                              void* d_out, int out_size)
{
    const float* z0 = (const float*)d_in[0];
    const float* t  = (const float*)d_in[1];
    const float* x  = (const float*)d_in[2];
    const float* W1 = (const float*)d_in[3];
    const float* Wx = (const float*)d_in[4];
    const float* wt = (const float*)d_in[5];
    const float* b1 = (const float*)d_in[6];
    const float* W2 = (const float*)d_in[7];
    const float* b2 = (const float*)d_in[8];
    float* out = (float*)d_out;

    const size_t smem = SMEM_FLOATS * sizeof(float);   // ~212 KB
    cudaFuncSetAttribute(ode_kernel,
                         cudaFuncAttributeMaxDynamicSharedMemorySize, (int)smem);
    ode_kernel<<<NCTA, NTH, smem>>>(z0, t, x, W1, Wx, wt, b1, W2, b2, out);
}